// round 1
// baseline (speedup 1.0000x reference)
#include <cuda_runtime.h>
#include <math.h>
#include <stdint.h>

// NF4 quantize-dequantize (straight-through forward): out = data_type[idx]*s
// s = per-row max|x| (clipped at 1e-6), idx = #{boundaries < x/s}  (searchsorted left)
//
// Strategy: one block per row. Row lives in registers (single HBM read).
// Per-row: exact absmax -> exact raw-x thresholds T_j (largest x with RN(x/s)<=b_j,
// refined with nextafter so per-element classification is bit-exact with the
// reference's divide-then-compare) -> 258-cell LUT over u = x*(128/s)+129.
// Per element: magic-FMA bin index, one LDS.128, one compare+select.

#define COLS 8192
#define NT 512
#define PERV 4            // float4 per thread (16 floats)
#define NB 15
#define NL 16
#define NCELL 258

__global__ __launch_bounds__(NT)
void nf4_kernel(const float* __restrict__ x,
                const float* __restrict__ bnd,
                const float* __restrict__ dt,
                float* __restrict__ out)
{
    __shared__ float4 table[NCELL];   // {T, vlo, vhi, pad}
    __shared__ float Tsm[NB];
    __shared__ float Vsm[NL];
    __shared__ float wmax[NT / 32];
    __shared__ float sS, c1S;

    const int row = blockIdx.x;
    const int tid = threadIdx.x;
    const float4* rp = (const float4*)(x + (size_t)row * COLS);
    float4* op = (float4*)(out + (size_t)row * COLS);

    // ---- Phase 1: load row into registers, compute absmax ----
    float4 v[PERV];
    float m = 0.0f;
#pragma unroll
    for (int i = 0; i < PERV; i++) {
        v[i] = rp[tid + i * NT];
        m = fmaxf(m, fabsf(v[i].x));
        m = fmaxf(m, fabsf(v[i].y));
        m = fmaxf(m, fabsf(v[i].z));
        m = fmaxf(m, fabsf(v[i].w));
    }
#pragma unroll
    for (int o = 16; o; o >>= 1) m = fmaxf(m, __shfl_xor_sync(0xffffffffu, m, o));
    if ((tid & 31) == 0) wmax[tid >> 5] = m;
    __syncthreads();
    if (tid == 0) {
        float s = wmax[0];
#pragma unroll
        for (int i = 1; i < NT / 32; i++) s = fmaxf(s, wmax[i]);
        s = fmaxf(s, 1e-6f);            // jnp.clip(..., 1e-6)
        sS = s;
        c1S = __fdiv_rn(128.0f, s);
    }
    __syncthreads();
    const float s = sS;

    // ---- Phase 2: exact thresholds in raw-x space + scaled levels ----
    // T_j = largest float t with RN(t/s) <= boundaries[j]. Then the reference's
    // (x/s > b_j) is exactly (x > T_j): no per-element division needed.
    if (tid < NB) {
        const float mid = __ldg(bnd + tid);
        float t = mid * s;
        for (int it = 0; it < 16 && __fdiv_rn(t, s) <= mid; it++)
            t = nextafterf(t, __int_as_float(0x7f800000));
        for (int it = 0; it < 16 && __fdiv_rn(t, s) > mid; it++)
            t = nextafterf(t, __int_as_float(0xff800000));
        Tsm[tid] = t;
    }
    if (tid >= 32 && tid < 32 + NL) {
        Vsm[tid - 32] = __ldg(dt + tid - 32) * s;   // RN, matches dt[idx]*s in ref
    }
    __syncthreads();

    // ---- Phase 3: build 258-cell LUT over u = x*c1 + 129, u in [1, 257] ----
    // Cell k holds x with x*c1 in [k-129.5, k-128.5] (+RN ties). Cell width
    // s/128 << min threshold gap (~0.085*s) => at most one threshold per
    // (padded) cell.
    {
        const float w = s * 0.0078125f;   // s/128 (exact pow2 scale, 1 rounding)
        const float padc = 0.05f * w;     // covers c1/w rounding + RN tie slop
        for (int k = tid; k < NCELL; k += NT) {
            const float L = ((float)k - 129.5f) * w - padc;
            const float R = ((float)k - 128.5f) * w + padc;
            int jb = 0;
#pragma unroll
            for (int jj = 0; jj < NB; jj++) jb += (Tsm[jj] < L) ? 1 : 0;
            float T = __int_as_float(0x7f800000);  // +inf: no boundary in cell
            float vlo, vhi;
            if (jb < NB && Tsm[jb] <= R) {
                T   = Tsm[jb];
                vlo = Vsm[jb];
                vhi = Vsm[jb + 1];
            } else {
                vlo = vhi = Vsm[jb];
            }
            table[k] = make_float4(T, vlo, vhi, 0.0f);
        }
    }
    __syncthreads();

    // ---- Phase 4: quantize from registers, one LDS.128 + cmp/sel per elem ----
    const float c1 = c1S;
    const float MAGIC = 8388608.0f + 129.0f;   // 2^23 + 129
#pragma unroll
    for (int i = 0; i < PERV; i++) {
        const float4 a = v[i];
        float4 q;
        {
            const int k = __float_as_int(fmaf(a.x, c1, MAGIC)) & 0x3ff;
            const float4 e = table[k];
            q.x = (a.x > e.x) ? e.z : e.y;
        }
        {
            const int k = __float_as_int(fmaf(a.y, c1, MAGIC)) & 0x3ff;
            const float4 e = table[k];
            q.y = (a.y > e.x) ? e.z : e.y;
        }
        {
            const int k = __float_as_int(fmaf(a.z, c1, MAGIC)) & 0x3ff;
            const float4 e = table[k];
            q.z = (a.z > e.x) ? e.z : e.y;
        }
        {
            const int k = __float_as_int(fmaf(a.w, c1, MAGIC)) & 0x3ff;
            const float4 e = table[k];
            q.w = (a.w > e.x) ? e.z : e.y;
        }
        op[tid + i * NT] = q;
    }
}

extern "C" void kernel_launch(void* const* d_in, const int* in_sizes, int n_in,
                              void* d_out, int out_size)
{
    // Identify inputs by size (robust to metadata ordering):
    const float* x = nullptr;
    const float* bnd = nullptr;
    const float* dt = nullptr;
    long long nx = 0;
    for (int i = 0; i < n_in; i++) {
        if (in_sizes[i] == NB)      bnd = (const float*)d_in[i];
        else if (in_sizes[i] == NL) dt  = (const float*)d_in[i];
        else { x = (const float*)d_in[i]; nx = in_sizes[i]; }
    }
    const int rows = (int)(nx / COLS);
    nf4_kernel<<<rows, NT>>>(x, bnd, dt, (float*)d_out);
}

// round 2
// speedup vs baseline: 1.0530x; 1.0530x over previous
#include <cuda_runtime.h>
#include <math.h>
#include <stdint.h>

// NF4 quantize-dequantize, straight-through forward: out = data_type[idx]*s,
// s = per-row max|x| (clip 1e-6), idx = searchsorted(boundaries, x/s, left).
//
// R2: persistent double-buffered pipeline. 296 blocks x 512 threads; each block
// owns rows bid, bid+296, ... Row r+1's LDGs are issued before row r's
// compute+store, so DRAM reads and writes overlap chip-wide (R1 showed
// phase-separated waves capping DRAM at 41%).
//
// Exactness: per-row thresholds T_j = largest float with RN(t/s) <= b_j
// (nextafter-refined), so per-element (x/s > b_j) == (x > T_j) bit-exactly.
// 258-cell LUT over u = x*(128/s) + 129 via magic-FMA; min boundary gap
// (~0.085*s) >> cell width (s/128) => <=1 threshold per cell.

#define COLS  8192
#define NT    512
#define PERV  4            // float4 per thread (16 floats) per buffer
#define NB    15
#define NL    16
#define NCELL 258
#define GRID  296          // 2 blocks per SM x 148 SMs

__device__ __forceinline__ float absmax16(const float4* v) {
    float m = 0.0f;
#pragma unroll
    for (int i = 0; i < PERV; i++) {
        m = fmaxf(m, fabsf(v[i].x));
        m = fmaxf(m, fabsf(v[i].y));
        m = fmaxf(m, fabsf(v[i].z));
        m = fmaxf(m, fabsf(v[i].w));
    }
    return m;
}

__global__ __launch_bounds__(NT, 2)
void nf4_kernel(const float* __restrict__ x,
                const float* __restrict__ bnd,
                const float* __restrict__ dt,
                float* __restrict__ out,
                int rows)
{
    __shared__ float4 table[NCELL];   // {T, vlo, vhi, pad}
    __shared__ float Tsm[NB];
    __shared__ float Vsm[NL];
    __shared__ float wmax[NT / 32];
    __shared__ float c1S;

    const int tid = threadIdx.x;
    const int lane = tid & 31;

    int r = blockIdx.x;
    if (r >= rows) return;

    // ---- prologue: load first row ----
    float4 va[PERV];
    {
        const float4* rp = (const float4*)(x + (size_t)r * COLS);
#pragma unroll
        for (int i = 0; i < PERV; i++) va[i] = rp[tid + i * NT];
    }
    float mA = absmax16(va);

    while (true) {
        // ---- block reduce absmax -> scale; build per-row tables ----
        float m = mA;
#pragma unroll
        for (int o = 16; o; o >>= 1) m = fmaxf(m, __shfl_xor_sync(0xffffffffu, m, o));
        if (lane == 0) wmax[tid >> 5] = m;
        __syncthreads();   // also fences prior iteration's table reads

        float s;
        {
            float t = wmax[0];
#pragma unroll
            for (int i = 1; i < NT / 32; i++) t = fmaxf(t, wmax[i]);
            s = fmaxf(t, 1e-6f);
        }
        if (tid == 0) c1S = __fdiv_rn(128.0f, s);
        // exact raw-x thresholds: largest t with RN(t/s) <= boundary
        if (tid < NB) {
            const float mid = __ldg(bnd + tid);
            float t = mid * s;
            for (int it = 0; it < 8 && __fdiv_rn(t, s) <= mid; it++)
                t = nextafterf(t, __int_as_float(0x7f800000));
            for (int it = 0; it < 8 && __fdiv_rn(t, s) > mid; it++)
                t = nextafterf(t, __int_as_float(0xff800000));
            Tsm[tid] = t;
        }
        if (tid >= 32 && tid < 32 + NL)
            Vsm[tid - 32] = __ldg(dt + tid - 32) * s;   // RN, matches dt[idx]*s
        __syncthreads();

        // 258-cell LUT over u = x*c1 + 129
        {
            const float w = s * 0.0078125f;   // s/128
            const float padc = 0.05f * w;
            for (int k = tid; k < NCELL; k += NT) {
                const float L = ((float)k - 129.5f) * w - padc;
                const float R = ((float)k - 128.5f) * w + padc;
                int jb = 0;
#pragma unroll
                for (int jj = 0; jj < NB; jj++) jb += (Tsm[jj] < L) ? 1 : 0;
                float T = __int_as_float(0x7f800000);
                float vlo, vhi;
                if (jb < NB && Tsm[jb] <= R) {
                    T = Tsm[jb]; vlo = Vsm[jb]; vhi = Vsm[jb + 1];
                } else {
                    vlo = vhi = Vsm[jb];
                }
                table[k] = make_float4(T, vlo, vhi, 0.0f);
            }
        }
        __syncthreads();
        const float c1 = c1S;

        // ---- issue prefetch LDGs for next row (no consumer yet) ----
        const int rn = r + GRID;
        float4 vb[PERV];
        if (rn < rows) {
            const float4* rp = (const float4*)(x + (size_t)rn * COLS);
#pragma unroll
            for (int i = 0; i < PERV; i++) vb[i] = rp[tid + i * NT];
        }

        // ---- quantize current row from registers; store (overlaps prefetch) ----
        {
            float4* op = (float4*)(out + (size_t)r * COLS);
            const float MAGIC = 8388608.0f + 129.0f;   // 2^23 + 129
#pragma unroll
            for (int i = 0; i < PERV; i++) {
                const float4 a = va[i];
                float4 q;
                {
                    const int k = __float_as_int(fmaf(a.x, c1, MAGIC)) & 0x3ff;
                    const float4 e = table[k];
                    q.x = (a.x > e.x) ? e.z : e.y;
                }
                {
                    const int k = __float_as_int(fmaf(a.y, c1, MAGIC)) & 0x3ff;
                    const float4 e = table[k];
                    q.y = (a.y > e.x) ? e.z : e.y;
                }
                {
                    const int k = __float_as_int(fmaf(a.z, c1, MAGIC)) & 0x3ff;
                    const float4 e = table[k];
                    q.z = (a.z > e.x) ? e.z : e.y;
                }
                {
                    const int k = __float_as_int(fmaf(a.w, c1, MAGIC)) & 0x3ff;
                    const float4 e = table[k];
                    q.w = (a.w > e.x) ? e.z : e.y;
                }
                op[tid + i * NT] = q;
            }
        }

        if (rn >= rows) break;

        // consume prefetched row (scoreboard wait lands here, after stores issued)
        mA = absmax16(vb);
#pragma unroll
        for (int i = 0; i < PERV; i++) va[i] = vb[i];
        r = rn;
    }
}

extern "C" void kernel_launch(void* const* d_in, const int* in_sizes, int n_in,
                              void* d_out, int out_size)
{
    const float* x = nullptr;
    const float* bnd = nullptr;
    const float* dt = nullptr;
    long long nx = 0;
    for (int i = 0; i < n_in; i++) {
        if (in_sizes[i] == NB)      bnd = (const float*)d_in[i];
        else if (in_sizes[i] == NL) dt  = (const float*)d_in[i];
        else { x = (const float*)d_in[i]; nx = in_sizes[i]; }
    }
    const int rows = (int)(nx / COLS);
    const int grid = rows < GRID ? rows : GRID;
    nf4_kernel<<<grid, NT>>>(x, bnd, dt, (float*)d_out, rows);
}